// round 1
// baseline (speedup 1.0000x reference)
#include <cuda_runtime.h>
#include <cuda_bf16.h>

#define N_NODES 50000
#define N_EDGES 800000
#define N_GRAPHS 500

// ---------------- device scratch (static; no allocation) ----------------
__device__ float g_feat[N_NODES * 128];
__device__ float g_h[N_NODES * 128];
__device__ float g_el[N_NODES * 4];
__device__ float g_er[N_NODES * 4];
__device__ int   g_rowptr[N_NODES + 1];
__device__ int   g_cnt[N_NODES];
__device__ int   g_fill[N_NODES];
__device__ int   g_csr[N_EDGES];
__device__ float g_bn[512];        // [0:128] sum0 [128:256] sumsq0 [256:384] sum1 [384:512] sumsq1
__device__ float g_ms[256];        // [0:128] mean [128:256] invstd (reused per layer)
__device__ float g_pool[N_GRAPHS * 32];

// ---------------- preprocessing: CSR by dst ----------------
__global__ void zero_kernel() {
    int i = blockIdx.x * blockDim.x + threadIdx.x;
    if (i < N_NODES) { g_cnt[i] = 0; g_fill[i] = 0; }
    if (i < 512) g_bn[i] = 0.f;
    if (i < N_GRAPHS * 32) g_pool[i] = 0.f;
}

__global__ void hist_kernel(const int* __restrict__ dst) {
    int i = blockIdx.x * blockDim.x + threadIdx.x;
    if (i < N_EDGES) atomicAdd(&g_cnt[dst[i]], 1);
}

__global__ void scan_kernel() {
    __shared__ int sh[1024];
    __shared__ int carry_sh;
    int t = threadIdx.x;
    if (t == 0) carry_sh = 0;
    __syncthreads();
    for (int base = 0; base < N_NODES; base += 1024) {
        int i = base + t;
        int v = (i < N_NODES) ? g_cnt[i] : 0;
        sh[t] = v;
        __syncthreads();
        for (int off = 1; off < 1024; off <<= 1) {
            int add = (t >= off) ? sh[t - off] : 0;
            __syncthreads();
            sh[t] += add;
            __syncthreads();
        }
        int incl = sh[t];
        int carry = carry_sh;
        if (i < N_NODES) g_rowptr[i] = carry + incl - v;
        __syncthreads();
        if (t == 1023) carry_sh = carry + incl;
        __syncthreads();
    }
    if (t == 0) g_rowptr[N_NODES] = carry_sh;
}

__global__ void scatter_kernel(const int* __restrict__ src, const int* __restrict__ dst) {
    int i = blockIdx.x * blockDim.x + threadIdx.x;
    if (i < N_EDGES) {
        int d = dst[i];
        int p = atomicAdd(&g_fill[d], 1);
        g_csr[g_rowptr[d] + p] = src[i];
    }
}

// ---------------- GEMM: C[M,BN] = A[M,128] @ W[128,BN] ----------------
template <int BN, int TN>
__global__ void gemm_kernel(const float* __restrict__ A, const float* __restrict__ W,
                            float* __restrict__ C, int M) {
    constexpr int BM = 64, BK = 16;
    __shared__ float As[BK][BM + 1];
    __shared__ float Bs[BK][BN];
    int tid = threadIdx.x;             // 256
    int tx = tid & 15, ty = tid >> 4;  // 16x16
    int row0 = blockIdx.x * BM;
    float acc[4][TN];
#pragma unroll
    for (int i = 0; i < 4; i++)
#pragma unroll
        for (int j = 0; j < TN; j++) acc[i][j] = 0.f;

    for (int k0 = 0; k0 < 128; k0 += BK) {
        {   // A tile: 64x16 = 256 float4
            int r = tid >> 2;
            int cs = tid & 3;
            int grow = row0 + r;
            float4 v = make_float4(0.f, 0.f, 0.f, 0.f);
            if (grow < M) v = *(const float4*)(A + grow * 128 + k0 + cs * 4);
            As[cs * 4 + 0][r] = v.x;
            As[cs * 4 + 1][r] = v.y;
            As[cs * 4 + 2][r] = v.z;
            As[cs * 4 + 3][r] = v.w;
        }
        {   // B tile: 16 x BN
            constexpr int NF4 = BK * BN / 4;
#pragma unroll
            for (int id = tid; id < NF4; id += 256) {
                int kr = id / (BN / 4);
                int c4 = id % (BN / 4);
                *(float4*)&Bs[kr][c4 * 4] = *(const float4*)(W + (k0 + kr) * BN + c4 * 4);
            }
        }
        __syncthreads();
#pragma unroll
        for (int kk = 0; kk < BK; kk++) {
            float a[4], b[TN];
#pragma unroll
            for (int i = 0; i < 4; i++) a[i] = As[kk][ty * 4 + i];
#pragma unroll
            for (int j = 0; j < TN; j++) b[j] = Bs[kk][tx * TN + j];
#pragma unroll
            for (int i = 0; i < 4; i++)
#pragma unroll
                for (int j = 0; j < TN; j++) acc[i][j] += a[i] * b[j];
        }
        __syncthreads();
    }
#pragma unroll
    for (int i = 0; i < 4; i++) {
        int r = row0 + ty * 4 + i;
        if (r < M) {
#pragma unroll
            for (int j = 0; j < TN; j++) C[r * BN + tx * TN + j] = acc[i][j];
        }
    }
}

// ---------------- el/er: per (node,head) attention scores ----------------
template <int H, int D, int F>
__global__ void elr_kernel(const float* __restrict__ feat, const float* __restrict__ al,
                           const float* __restrict__ ar, float* __restrict__ el,
                           float* __restrict__ er) {
    int i = blockIdx.x * blockDim.x + threadIdx.x;
    if (i >= N_NODES * H) return;
    int n = i / H, h = i % H;
    const float4* f4 = (const float4*)(feat + n * F + h * D);
    const float4* a4 = (const float4*)(al + h * D);
    const float4* r4 = (const float4*)(ar + h * D);
    float sl = 0.f, sr = 0.f;
#pragma unroll
    for (int d = 0; d < D / 4; d++) {
        float4 f = f4[d], a = a4[d], r = r4[d];
        sl += f.x * a.x + f.y * a.y + f.z * a.z + f.w * a.w;
        sr += f.x * r.x + f.y * r.y + f.z * r.z + f.w * r.w;
    }
    el[i] = sl;
    er[i] = sr;
}

// ---------------- edge-softmax + aggregation: warp per (node,head) ----------------
template <int H, int D, int F>
__global__ void agg_kernel(const float* __restrict__ feat, const float* __restrict__ el,
                           const float* __restrict__ er, const float* __restrict__ bias,
                           float* __restrict__ out) {
    int wg = blockIdx.x * (blockDim.x >> 5) + (threadIdx.x >> 5);
    int lane = threadIdx.x & 31;
    if (wg >= N_NODES * H) return;
    int n = wg / H, h = wg % H;
    int start = g_rowptr[n], end = g_rowptr[n + 1];
    float ern = er[n * H + h];

    float m = -1e30f;
    for (int e = start + lane; e < end; e += 32) {
        int s = g_csr[e];
        float sc = el[s * H + h] + ern;
        sc = sc > 0.f ? sc : 0.2f * sc;
        m = fmaxf(m, sc);
    }
#pragma unroll
    for (int off = 16; off; off >>= 1) m = fmaxf(m, __shfl_xor_sync(0xffffffffu, m, off));

    float acc = 0.f, denom = 0.f;
    for (int e = start; e < end; e++) {
        int s = g_csr[e];
        float sc = el[s * H + h] + ern;
        sc = sc > 0.f ? sc : 0.2f * sc;
        float w = __expf(sc - m);
        denom += w;
        acc += w * feat[s * F + h * D + lane];
    }
    float o = bias[h * D + lane];
    if (end > start) o += acc / denom;
    out[n * F + h * D + lane] = o;
}

// ---------------- batch norm ----------------
__global__ void bn_stats_kernel(const float* __restrict__ h, int off) {
    int c = threadIdx.x;  // 128
    float s = 0.f, s2 = 0.f;
    for (int r = blockIdx.x; r < N_NODES; r += gridDim.x) {
        float v = h[r * 128 + c];
        s += v;
        s2 += v * v;
    }
    atomicAdd(&g_bn[off + c], s);
    atomicAdd(&g_bn[off + 128 + c], s2);
}

__global__ void bn_fin_kernel(int off) {
    int c = threadIdx.x;
    float mu = g_bn[off + c] * (1.f / N_NODES);
    float var = g_bn[off + 128 + c] * (1.f / N_NODES) - mu * mu;
    g_ms[c] = mu;
    g_ms[128 + c] = rsqrtf(var + 1e-5f);
}

__global__ void bn_norm_relu_kernel(float* __restrict__ h, const float* __restrict__ gamma,
                                    const float* __restrict__ beta) {
    int i = blockIdx.x * blockDim.x + threadIdx.x;
    if (i >= N_NODES * 32) return;
    int c4 = i & 31;
    float4 v = ((float4*)h)[i];
    float4 mu = ((const float4*)g_ms)[c4];
    float4 is = ((const float4*)(g_ms + 128))[c4];
    float4 ga = ((const float4*)gamma)[c4];
    float4 be = ((const float4*)beta)[c4];
    v.x = fmaxf(ga.x * (v.x - mu.x) * is.x + be.x, 0.f);
    v.y = fmaxf(ga.y * (v.y - mu.y) * is.y + be.y, 0.f);
    v.z = fmaxf(ga.z * (v.z - mu.z) * is.z + be.z, 0.f);
    v.w = fmaxf(ga.w * (v.w - mu.w) * is.w + be.w, 0.f);
    ((float4*)h)[i] = v;
}

// ---------------- pooling + classifier ----------------
__global__ void pool_kernel(const float* __restrict__ h2, const int* __restrict__ gid) {
    int i = blockIdx.x * blockDim.x + threadIdx.x;
    if (i >= N_NODES * 32) return;
    int n = i >> 5, c = i & 31;
    atomicAdd(&g_pool[gid[n] * 32 + c], h2[n * 32 + c]);
}

__global__ void cls_kernel(const float* __restrict__ Wc, const float* __restrict__ bc,
                           float* __restrict__ out) {
    int g = blockIdx.x;
    int t = threadIdx.x;
    if (t < 10) {
        float s = bc[t];
#pragma unroll
        for (int k = 0; k < 32; k++) s += g_pool[g * 32 + k] * Wc[k * 10 + t];
        out[g * 10 + t] = s;
    }
}

// ---------------- host launcher ----------------
extern "C" void kernel_launch(void* const* d_in, const int* in_sizes, int n_in,
                              void* d_out, int out_size) {
    const float* x   = (const float*)d_in[0];
    const int* esrc  = (const int*)d_in[1];
    const int* edst  = (const int*)d_in[2];
    const int* gid   = (const int*)d_in[3];
    const float* W0  = (const float*)d_in[4];
    const float* al0 = (const float*)d_in[5];
    const float* ar0 = (const float*)d_in[6];
    const float* b0  = (const float*)d_in[7];
    const float* W1  = (const float*)d_in[8];
    const float* al1 = (const float*)d_in[9];
    const float* ar1 = (const float*)d_in[10];
    const float* b1  = (const float*)d_in[11];
    const float* W2  = (const float*)d_in[12];
    const float* al2 = (const float*)d_in[13];
    const float* ar2 = (const float*)d_in[14];
    const float* b2  = (const float*)d_in[15];
    const float* g0  = (const float*)d_in[16];
    const float* be0 = (const float*)d_in[17];
    const float* g1  = (const float*)d_in[18];
    const float* be1 = (const float*)d_in[19];
    const float* Wc  = (const float*)d_in[20];
    const float* bc  = (const float*)d_in[21];
    float* out = (float*)d_out;

    float *feat, *h, *el, *er;
    cudaGetSymbolAddress((void**)&feat, g_feat);
    cudaGetSymbolAddress((void**)&h, g_h);
    cudaGetSymbolAddress((void**)&el, g_el);
    cudaGetSymbolAddress((void**)&er, g_er);

    // preprocessing: CSR by dst (rebuilt each launch; deterministic work)
    zero_kernel<<<(N_NODES + 255) / 256, 256>>>();
    hist_kernel<<<(N_EDGES + 255) / 256, 256>>>(edst);
    scan_kernel<<<1, 1024>>>();
    scatter_kernel<<<(N_EDGES + 255) / 256, 256>>>(esrc, edst);

    const int gemm_blocks = (N_NODES + 63) / 64;

    // ---- layer 0 ----
    gemm_kernel<128, 8><<<gemm_blocks, 256>>>(x, W0, feat, N_NODES);
    elr_kernel<4, 32, 128><<<(N_NODES * 4 + 255) / 256, 256>>>(feat, al0, ar0, el, er);
    agg_kernel<4, 32, 128><<<N_NODES, 128>>>(feat, el, er, b0, h);
    bn_stats_kernel<<<256, 128>>>(h, 0);
    bn_fin_kernel<<<1, 128>>>(0);
    bn_norm_relu_kernel<<<(N_NODES * 32 + 255) / 256, 256>>>(h, g0, be0);

    // ---- layer 1 ----
    gemm_kernel<128, 8><<<gemm_blocks, 256>>>(h, W1, feat, N_NODES);
    elr_kernel<4, 32, 128><<<(N_NODES * 4 + 255) / 256, 256>>>(feat, al1, ar1, el, er);
    agg_kernel<4, 32, 128><<<N_NODES, 128>>>(feat, el, er, b1, h);
    bn_stats_kernel<<<256, 128>>>(h, 256);
    bn_fin_kernel<<<1, 128>>>(256);
    bn_norm_relu_kernel<<<(N_NODES * 32 + 255) / 256, 256>>>(h, g1, be1);

    // ---- layer 2 (H=1, D=32) ----
    gemm_kernel<32, 2><<<gemm_blocks, 256>>>(h, W2, feat, N_NODES);
    elr_kernel<1, 32, 32><<<(N_NODES + 255) / 256, 256>>>(feat, al2, ar2, el, er);
    agg_kernel<1, 32, 32><<<(N_NODES + 3) / 4, 128>>>(feat, el, er, b2, h);

    // ---- pooling + classifier ----
    pool_kernel<<<(N_NODES * 32 + 255) / 256, 256>>>(h, gid);
    cls_kernel<<<N_GRAPHS, 32>>>(Wc, bc, out);
}

// round 2
// speedup vs baseline: 1.4074x; 1.4074x over previous
#include <cuda_runtime.h>
#include <cuda_bf16.h>

#define N_NODES 50000
#define N_EDGES 800000
#define N_GRAPHS 500
#define NBLK_SCAN ((N_NODES + 511) / 512)   // 98

// ---------------- device scratch (static; no allocation) ----------------
__device__ float g_feat[N_NODES * 128];
__device__ float g_h[N_NODES * 128];
__device__ float g_el[N_NODES * 4];
__device__ float g_er[N_NODES * 4];
__device__ int   g_rowptr[N_NODES + 1];
__device__ int   g_cnt[N_NODES];
__device__ int   g_fill[N_NODES];
__device__ int   g_csr[N_EDGES];     // src node per sorted (by dst) edge slot
__device__ int   g_edst[N_EDGES];    // dst node per sorted edge slot
__device__ float g_w[N_EDGES * 4];   // per-edge per-head unnormalized softmax weight
__device__ int   g_bsum[128];
__device__ int   g_boff[128];
__device__ float g_bn[512];
__device__ float g_ms[256];
__device__ float g_pool[N_GRAPHS * 32];

// ---------------- preprocessing: CSR by dst ----------------
__global__ void zero_kernel() {
    int i = blockIdx.x * blockDim.x + threadIdx.x;
    if (i < N_NODES) { g_cnt[i] = 0; g_fill[i] = 0; }
    if (i < 512) g_bn[i] = 0.f;
    if (i < N_GRAPHS * 32) g_pool[i] = 0.f;
}

__global__ void hist_kernel(const int* __restrict__ dst) {
    int i = blockIdx.x * blockDim.x + threadIdx.x;
    if (i < N_EDGES) atomicAdd(&g_cnt[dst[i]], 1);
}

__global__ void scan_reduce_kernel() {  // NBLK_SCAN x 512
    __shared__ int sh[512];
    int t = threadIdx.x;
    int i = blockIdx.x * 512 + t;
    sh[t] = (i < N_NODES) ? g_cnt[i] : 0;
    __syncthreads();
#pragma unroll
    for (int off = 256; off; off >>= 1) {
        if (t < off) sh[t] += sh[t + off];
        __syncthreads();
    }
    if (t == 0) g_bsum[blockIdx.x] = sh[0];
}

__global__ void scan_top_kernel() {  // 1 x 128
    __shared__ int sh[128];
    int t = threadIdx.x;
    int v = (t < NBLK_SCAN) ? g_bsum[t] : 0;
    sh[t] = v;
    __syncthreads();
#pragma unroll
    for (int off = 1; off < 128; off <<= 1) {
        int add = (t >= off) ? sh[t - off] : 0;
        __syncthreads();
        sh[t] += add;
        __syncthreads();
    }
    g_boff[t] = sh[t] - v;  // exclusive
    if (t == 127) g_rowptr[N_NODES] = sh[127];
}

__global__ void scan_final_kernel() {  // NBLK_SCAN x 512
    __shared__ int sh[512];
    int t = threadIdx.x;
    int i = blockIdx.x * 512 + t;
    int v = (i < N_NODES) ? g_cnt[i] : 0;
    sh[t] = v;
    __syncthreads();
#pragma unroll
    for (int off = 1; off < 512; off <<= 1) {
        int add = (t >= off) ? sh[t - off] : 0;
        __syncthreads();
        sh[t] += add;
        __syncthreads();
    }
    if (i < N_NODES) g_rowptr[i] = g_boff[blockIdx.x] + sh[t] - v;
}

__global__ void scatter_kernel(const int* __restrict__ src, const int* __restrict__ dst) {
    int i = blockIdx.x * blockDim.x + threadIdx.x;
    if (i < N_EDGES) {
        int d = dst[i];
        int p = atomicAdd(&g_fill[d], 1);
        int pos = g_rowptr[d] + p;
        g_csr[pos] = src[i];
        g_edst[pos] = d;
    }
}

// ---------------- GEMM: C[M,BN] = A[M,128] @ W[128,BN] ----------------
template <int BN, int TN>
__global__ void gemm_kernel(const float* __restrict__ A, const float* __restrict__ W,
                            float* __restrict__ C, int M) {
    constexpr int BM = 64, BK = 16;
    __shared__ float As[BK][BM + 1];
    __shared__ float Bs[BK][BN];
    int tid = threadIdx.x;             // 256
    int tx = tid & 15, ty = tid >> 4;  // 16x16
    int row0 = blockIdx.x * BM;
    float acc[4][TN];
#pragma unroll
    for (int i = 0; i < 4; i++)
#pragma unroll
        for (int j = 0; j < TN; j++) acc[i][j] = 0.f;

    for (int k0 = 0; k0 < 128; k0 += BK) {
        {
            int r = tid >> 2;
            int cs = tid & 3;
            int grow = row0 + r;
            float4 v = make_float4(0.f, 0.f, 0.f, 0.f);
            if (grow < M) v = *(const float4*)(A + grow * 128 + k0 + cs * 4);
            As[cs * 4 + 0][r] = v.x;
            As[cs * 4 + 1][r] = v.y;
            As[cs * 4 + 2][r] = v.z;
            As[cs * 4 + 3][r] = v.w;
        }
        {
            constexpr int NF4 = BK * BN / 4;
#pragma unroll
            for (int id = tid; id < NF4; id += 256) {
                int kr = id / (BN / 4);
                int c4 = id % (BN / 4);
                *(float4*)&Bs[kr][c4 * 4] = *(const float4*)(W + (k0 + kr) * BN + c4 * 4);
            }
        }
        __syncthreads();
#pragma unroll
        for (int kk = 0; kk < BK; kk++) {
            float a[4], b[TN];
#pragma unroll
            for (int i = 0; i < 4; i++) a[i] = As[kk][ty * 4 + i];
#pragma unroll
            for (int j = 0; j < TN; j++) b[j] = Bs[kk][tx * TN + j];
#pragma unroll
            for (int i = 0; i < 4; i++)
#pragma unroll
                for (int j = 0; j < TN; j++) acc[i][j] += a[i] * b[j];
        }
        __syncthreads();
    }
#pragma unroll
    for (int i = 0; i < 4; i++) {
        int r = row0 + ty * 4 + i;
        if (r < M) {
#pragma unroll
            for (int j = 0; j < TN; j++) C[r * BN + tx * TN + j] = acc[i][j];
        }
    }
}

// ---------------- el/er: per (node,head) attention scores ----------------
template <int H, int D, int F>
__global__ void elr_kernel(const float* __restrict__ feat, const float* __restrict__ al,
                           const float* __restrict__ ar, float* __restrict__ el,
                           float* __restrict__ er) {
    int i = blockIdx.x * blockDim.x + threadIdx.x;
    if (i >= N_NODES * H) return;
    int n = i / H, h = i % H;
    const float4* f4 = (const float4*)(feat + n * F + h * D);
    const float4* a4 = (const float4*)(al + h * D);
    const float4* r4 = (const float4*)(ar + h * D);
    float sl = 0.f, sr = 0.f;
#pragma unroll
    for (int d = 0; d < D / 4; d++) {
        float4 f = f4[d], a = a4[d], r = r4[d];
        sl += f.x * a.x + f.y * a.y + f.z * a.z + f.w * a.w;
        sr += f.x * r.x + f.y * r.y + f.z * r.z + f.w * r.w;
    }
    el[i] = sl;
    er[i] = sr;
}

// ---------------- per-edge weights: w = exp(leaky(el[s]+er[d])) ----------------
__global__ void w4_kernel(const float* __restrict__ el, const float* __restrict__ er) {
    int pos = blockIdx.x * blockDim.x + threadIdx.x;
    if (pos >= N_EDGES) return;
    int s = g_csr[pos], d = g_edst[pos];
    float4 l = *(const float4*)(el + s * 4);
    float4 r = *(const float4*)(er + d * 4);
    float4 w;
    float e;
    e = l.x + r.x; e = e > 0.f ? e : 0.2f * e; w.x = __expf(e);
    e = l.y + r.y; e = e > 0.f ? e : 0.2f * e; w.y = __expf(e);
    e = l.z + r.z; e = e > 0.f ? e : 0.2f * e; w.z = __expf(e);
    e = l.w + r.w; e = e > 0.f ? e : 0.2f * e; w.w = __expf(e);
    *(float4*)(g_w + pos * 4) = w;
}

__global__ void w1_kernel(const float* __restrict__ el, const float* __restrict__ er) {
    int pos = blockIdx.x * blockDim.x + threadIdx.x;
    if (pos >= N_EDGES) return;
    int s = g_csr[pos], d = g_edst[pos];
    float e = el[s] + er[d];
    e = e > 0.f ? e : 0.2f * e;
    g_w[pos] = __expf(e);
}

// ---------------- aggregation (H=4, D=32): warp per node ----------------
__global__ void agg4_kernel(const float* __restrict__ feat, const float* __restrict__ bias,
                            float* __restrict__ out) {
    int n = blockIdx.x * (blockDim.x >> 5) + (threadIdx.x >> 5);
    int lane = threadIdx.x & 31;
    if (n >= N_NODES) return;
    int start = g_rowptr[n], end = g_rowptr[n + 1];
    int head = lane >> 3;  // lane covers channels [lane*4, lane*4+4)

    float4 acc = make_float4(0.f, 0.f, 0.f, 0.f);
    float denom = 0.f;
    int e = start;
    for (; e + 2 <= end; e += 2) {
        int s0 = __ldg(&g_csr[e]);
        int s1 = __ldg(&g_csr[e + 1]);
        float w0 = __ldg(&g_w[e * 4 + head]);
        float w1 = __ldg(&g_w[(e + 1) * 4 + head]);
        float4 f0 = *(const float4*)(feat + s0 * 128 + lane * 4);
        float4 f1 = *(const float4*)(feat + s1 * 128 + lane * 4);
        acc.x += w0 * f0.x + w1 * f1.x;
        acc.y += w0 * f0.y + w1 * f1.y;
        acc.z += w0 * f0.z + w1 * f1.z;
        acc.w += w0 * f0.w + w1 * f1.w;
        denom += w0 + w1;
    }
    if (e < end) {
        int s0 = __ldg(&g_csr[e]);
        float w0 = __ldg(&g_w[e * 4 + head]);
        float4 f0 = *(const float4*)(feat + s0 * 128 + lane * 4);
        acc.x += w0 * f0.x;
        acc.y += w0 * f0.y;
        acc.z += w0 * f0.z;
        acc.w += w0 * f0.w;
        denom += w0;
    }
    float4 b = *(const float4*)(bias + lane * 4);
    if (end > start) {
        float inv = 1.f / denom;
        b.x += acc.x * inv;
        b.y += acc.y * inv;
        b.z += acc.z * inv;
        b.w += acc.w * inv;
    }
    *(float4*)(out + n * 128 + lane * 4) = b;
}

// ---------------- aggregation (H=1, D=32): warp per node ----------------
__global__ void agg1_kernel(const float* __restrict__ feat, const float* __restrict__ bias,
                            float* __restrict__ out) {
    int n = blockIdx.x * (blockDim.x >> 5) + (threadIdx.x >> 5);
    int lane = threadIdx.x & 31;
    if (n >= N_NODES) return;
    int start = g_rowptr[n], end = g_rowptr[n + 1];

    float acc = 0.f, denom = 0.f;
    int e = start;
    for (; e + 2 <= end; e += 2) {
        int s0 = __ldg(&g_csr[e]);
        int s1 = __ldg(&g_csr[e + 1]);
        float w0 = __ldg(&g_w[e]);
        float w1 = __ldg(&g_w[e + 1]);
        float f0 = __ldg(feat + s0 * 32 + lane);
        float f1 = __ldg(feat + s1 * 32 + lane);
        acc += w0 * f0 + w1 * f1;
        denom += w0 + w1;
    }
    if (e < end) {
        int s0 = __ldg(&g_csr[e]);
        float w0 = __ldg(&g_w[e]);
        acc += w0 * __ldg(feat + s0 * 32 + lane);
        denom += w0;
    }
    float o = bias[lane];
    if (end > start) o += acc / denom;
    out[n * 32 + lane] = o;
}

// ---------------- batch norm ----------------
__global__ void bn_stats_kernel(const float* __restrict__ h, int off) {
    int c = threadIdx.x;  // 128
    float s = 0.f, s2 = 0.f;
    for (int r = blockIdx.x; r < N_NODES; r += gridDim.x) {
        float v = h[r * 128 + c];
        s += v;
        s2 += v * v;
    }
    atomicAdd(&g_bn[off + c], s);
    atomicAdd(&g_bn[off + 128 + c], s2);
}

__global__ void bn_fin_kernel(int off) {
    int c = threadIdx.x;
    float mu = g_bn[off + c] * (1.f / N_NODES);
    float var = g_bn[off + 128 + c] * (1.f / N_NODES) - mu * mu;
    g_ms[c] = mu;
    g_ms[128 + c] = rsqrtf(var + 1e-5f);
}

__global__ void bn_norm_relu_kernel(float* __restrict__ h, const float* __restrict__ gamma,
                                    const float* __restrict__ beta) {
    int i = blockIdx.x * blockDim.x + threadIdx.x;
    if (i >= N_NODES * 32) return;
    int c4 = i & 31;
    float4 v = ((float4*)h)[i];
    float4 mu = ((const float4*)g_ms)[c4];
    float4 is = ((const float4*)(g_ms + 128))[c4];
    float4 ga = ((const float4*)gamma)[c4];
    float4 be = ((const float4*)beta)[c4];
    v.x = fmaxf(ga.x * (v.x - mu.x) * is.x + be.x, 0.f);
    v.y = fmaxf(ga.y * (v.y - mu.y) * is.y + be.y, 0.f);
    v.z = fmaxf(ga.z * (v.z - mu.z) * is.z + be.z, 0.f);
    v.w = fmaxf(ga.w * (v.w - mu.w) * is.w + be.w, 0.f);
    ((float4*)h)[i] = v;
}

// ---------------- pooling + classifier ----------------
__global__ void pool_kernel(const float* __restrict__ h2, const int* __restrict__ gid) {
    int i = blockIdx.x * blockDim.x + threadIdx.x;
    if (i >= N_NODES * 32) return;
    int n = i >> 5, c = i & 31;
    atomicAdd(&g_pool[gid[n] * 32 + c], h2[n * 32 + c]);
}

__global__ void cls_kernel(const float* __restrict__ Wc, const float* __restrict__ bc,
                           float* __restrict__ out) {
    int g = blockIdx.x;
    int t = threadIdx.x;
    if (t < 10) {
        float s = bc[t];
#pragma unroll
        for (int k = 0; k < 32; k++) s += g_pool[g * 32 + k] * Wc[k * 10 + t];
        out[g * 10 + t] = s;
    }
}

// ---------------- host launcher ----------------
extern "C" void kernel_launch(void* const* d_in, const int* in_sizes, int n_in,
                              void* d_out, int out_size) {
    const float* x   = (const float*)d_in[0];
    const int* esrc  = (const int*)d_in[1];
    const int* edst  = (const int*)d_in[2];
    const int* gid   = (const int*)d_in[3];
    const float* W0  = (const float*)d_in[4];
    const float* al0 = (const float*)d_in[5];
    const float* ar0 = (const float*)d_in[6];
    const float* b0  = (const float*)d_in[7];
    const float* W1  = (const float*)d_in[8];
    const float* al1 = (const float*)d_in[9];
    const float* ar1 = (const float*)d_in[10];
    const float* b1  = (const float*)d_in[11];
    const float* W2  = (const float*)d_in[12];
    const float* al2 = (const float*)d_in[13];
    const float* ar2 = (const float*)d_in[14];
    const float* b2  = (const float*)d_in[15];
    const float* g0  = (const float*)d_in[16];
    const float* be0 = (const float*)d_in[17];
    const float* g1  = (const float*)d_in[18];
    const float* be1 = (const float*)d_in[19];
    const float* Wc  = (const float*)d_in[20];
    const float* bc  = (const float*)d_in[21];
    float* out = (float*)d_out;

    float *feat, *h, *el, *er;
    cudaGetSymbolAddress((void**)&feat, g_feat);
    cudaGetSymbolAddress((void**)&h, g_h);
    cudaGetSymbolAddress((void**)&el, g_el);
    cudaGetSymbolAddress((void**)&er, g_er);

    // preprocessing: CSR by dst
    zero_kernel<<<(N_NODES + 255) / 256, 256>>>();
    hist_kernel<<<(N_EDGES + 255) / 256, 256>>>(edst);
    scan_reduce_kernel<<<NBLK_SCAN, 512>>>();
    scan_top_kernel<<<1, 128>>>();
    scan_final_kernel<<<NBLK_SCAN, 512>>>();
    scatter_kernel<<<(N_EDGES + 255) / 256, 256>>>(esrc, edst);

    const int gemm_blocks = (N_NODES + 63) / 64;
    const int eblocks = (N_EDGES + 255) / 256;
    const int nwarp_blocks = (N_NODES + 7) / 8;   // 8 warps per block of 256

    // ---- layer 0 ----
    gemm_kernel<128, 8><<<gemm_blocks, 256>>>(x, W0, feat, N_NODES);
    elr_kernel<4, 32, 128><<<(N_NODES * 4 + 255) / 256, 256>>>(feat, al0, ar0, el, er);
    w4_kernel<<<eblocks, 256>>>(el, er);
    agg4_kernel<<<nwarp_blocks, 256>>>(feat, b0, h);
    bn_stats_kernel<<<256, 128>>>(h, 0);
    bn_fin_kernel<<<1, 128>>>(0);
    bn_norm_relu_kernel<<<(N_NODES * 32 + 255) / 256, 256>>>(h, g0, be0);

    // ---- layer 1 ----
    gemm_kernel<128, 8><<<gemm_blocks, 256>>>(h, W1, feat, N_NODES);
    elr_kernel<4, 32, 128><<<(N_NODES * 4 + 255) / 256, 256>>>(feat, al1, ar1, el, er);
    w4_kernel<<<eblocks, 256>>>(el, er);
    agg4_kernel<<<nwarp_blocks, 256>>>(feat, b1, h);
    bn_stats_kernel<<<256, 128>>>(h, 256);
    bn_fin_kernel<<<1, 128>>>(256);
    bn_norm_relu_kernel<<<(N_NODES * 32 + 255) / 256, 256>>>(h, g1, be1);

    // ---- layer 2 (H=1, D=32) ----
    gemm_kernel<32, 2><<<gemm_blocks, 256>>>(h, W2, feat, N_NODES);
    elr_kernel<1, 32, 32><<<(N_NODES + 255) / 256, 256>>>(feat, al2, ar2, el, er);
    w1_kernel<<<eblocks, 256>>>(el, er);
    agg1_kernel<<<nwarp_blocks, 256>>>(feat, b2, h);

    // ---- pooling + classifier ----
    pool_kernel<<<(N_NODES * 32 + 255) / 256, 256>>>(h, gid);
    cls_kernel<<<N_GRAPHS, 32>>>(Wc, bc, out);
}

// round 3
// speedup vs baseline: 1.6847x; 1.1970x over previous
#include <cuda_runtime.h>
#include <cuda_bf16.h>

#define N_NODES 50000
#define N_EDGES 800000
#define N_GRAPHS 500
#define NBLK_SCAN ((N_NODES + 511) / 512)   // 98

typedef unsigned long long ull;

__device__ __forceinline__ ull pack2(float x, float y) {
    ull d; asm("mov.b64 %0, {%1, %2};" : "=l"(d) : "f"(x), "f"(y)); return d;
}
__device__ __forceinline__ float2 unpack2(ull d) {
    float2 r; asm("mov.b64 {%0, %1}, %2;" : "=f"(r.x), "=f"(r.y) : "l"(d)); return r;
}
__device__ __forceinline__ void ffma2(ull& d, ull a, ull b) {
    asm("fma.rn.f32x2 %0, %1, %2, %3;" : "=l"(d) : "l"(a), "l"(b), "l"(d));
}

// ---------------- device scratch (static; no allocation) ----------------
__device__ float g_feat[N_NODES * 128];
__device__ float g_h[N_NODES * 128];
__device__ float g_el[N_NODES * 4];
__device__ float g_er[N_NODES * 4];
__device__ int   g_rowptr[N_NODES + 1];
__device__ int   g_cnt[N_NODES];
__device__ int   g_fill[N_NODES];
__device__ int   g_csr[N_EDGES];
__device__ int   g_edst[N_EDGES];
__device__ int   g_bsum[128];
__device__ int   g_boff[128];
__device__ float g_bn[512];
__device__ float g_ms[256];   // [0:128] scale  [128:256] shift
__device__ float g_pool[N_GRAPHS * 32];

// ---------------- preprocessing: CSR by dst ----------------
__global__ void zero_kernel() {
    int i = blockIdx.x * blockDim.x + threadIdx.x;
    if (i < N_NODES) { g_cnt[i] = 0; g_fill[i] = 0; }
    if (i < 512) g_bn[i] = 0.f;
    if (i < N_GRAPHS * 32) g_pool[i] = 0.f;
}

__global__ void hist_kernel(const int* __restrict__ dst) {
    int i = blockIdx.x * blockDim.x + threadIdx.x;
    if (i < N_EDGES) atomicAdd(&g_cnt[dst[i]], 1);
}

__global__ void scan_reduce_kernel() {
    __shared__ int sh[512];
    int t = threadIdx.x;
    int i = blockIdx.x * 512 + t;
    sh[t] = (i < N_NODES) ? g_cnt[i] : 0;
    __syncthreads();
#pragma unroll
    for (int off = 256; off; off >>= 1) {
        if (t < off) sh[t] += sh[t + off];
        __syncthreads();
    }
    if (t == 0) g_bsum[blockIdx.x] = sh[0];
}

__global__ void scan_top_kernel() {
    __shared__ int sh[128];
    int t = threadIdx.x;
    int v = (t < NBLK_SCAN) ? g_bsum[t] : 0;
    sh[t] = v;
    __syncthreads();
#pragma unroll
    for (int off = 1; off < 128; off <<= 1) {
        int add = (t >= off) ? sh[t - off] : 0;
        __syncthreads();
        sh[t] += add;
        __syncthreads();
    }
    g_boff[t] = sh[t] - v;
    if (t == 127) g_rowptr[N_NODES] = sh[127];
}

__global__ void scan_final_kernel() {
    __shared__ int sh[512];
    int t = threadIdx.x;
    int i = blockIdx.x * 512 + t;
    int v = (i < N_NODES) ? g_cnt[i] : 0;
    sh[t] = v;
    __syncthreads();
#pragma unroll
    for (int off = 1; off < 512; off <<= 1) {
        int add = (t >= off) ? sh[t - off] : 0;
        __syncthreads();
        sh[t] += add;
        __syncthreads();
    }
    if (i < N_NODES) g_rowptr[i] = g_boff[blockIdx.x] + sh[t] - v;
}

__global__ void scatter_kernel(const int* __restrict__ src, const int* __restrict__ dst) {
    int i = blockIdx.x * blockDim.x + threadIdx.x;
    if (i < N_EDGES) {
        int d = dst[i];
        int p = atomicAdd(&g_fill[d], 1);
        int pos = g_rowptr[d] + p;
        g_csr[pos] = src[i];
        g_edst[pos] = d;
    }
}

// ---------------- GEMM: C[M,BN] = normrelu?(A[M,128]) @ W[128,BN], f32x2 FMA ----
// BM=128, BK=8, 256 threads (16x16), TM=8, TN = 8 or 2.
template <int BN, int TN, bool NORM>
__global__ void gemm2_kernel(const float* __restrict__ A, const float* __restrict__ W,
                             float* __restrict__ C, int M) {
    constexpr int BM = 128, BK = 8;
    __shared__ float As[BK][BM + 4];
    __shared__ float Bs[BK][BN];
    int tid = threadIdx.x;
    int tx = tid & 15, ty = tid >> 4;
    int row0 = blockIdx.x * BM;

    ull acc[8][TN / 2];
#pragma unroll
    for (int i = 0; i < 8; i++)
#pragma unroll
        for (int j = 0; j < TN / 2; j++) acc[i][j] = 0ull;

    int ar = tid >> 1;          // A row within tile
    int ac4 = tid & 1;          // which float4 of the BK=8 row segment
    int grow = row0 + ar;

    for (int k0 = 0; k0 < 128; k0 += BK) {
        // A tile (with optional fused BN-normalize + ReLU)
        {
            float4 v = make_float4(0.f, 0.f, 0.f, 0.f);
            if (grow < M) v = *(const float4*)(A + grow * 128 + k0 + ac4 * 4);
            if (NORM) {
                int k = k0 + ac4 * 4;
                v.x = fmaxf(v.x * g_ms[k + 0] + g_ms[128 + k + 0], 0.f);
                v.y = fmaxf(v.y * g_ms[k + 1] + g_ms[128 + k + 1], 0.f);
                v.z = fmaxf(v.z * g_ms[k + 2] + g_ms[128 + k + 2], 0.f);
                v.w = fmaxf(v.w * g_ms[k + 3] + g_ms[128 + k + 3], 0.f);
            }
            As[ac4 * 4 + 0][ar] = v.x;
            As[ac4 * 4 + 1][ar] = v.y;
            As[ac4 * 4 + 2][ar] = v.z;
            As[ac4 * 4 + 3][ar] = v.w;
        }
        // B tile: BK x BN
        {
            constexpr int NF4 = BK * BN / 4;
#pragma unroll
            for (int id = tid; id < NF4; id += 256) {
                int kr = id / (BN / 4);
                int c4 = id % (BN / 4);
                *(float4*)&Bs[kr][c4 * 4] = *(const float4*)(W + (k0 + kr) * BN + c4 * 4);
            }
        }
        __syncthreads();
#pragma unroll
        for (int kk = 0; kk < BK; kk++) {
            float4 a0 = *(const float4*)&As[kk][ty * 8];
            float4 a1 = *(const float4*)&As[kk][ty * 8 + 4];
            ull aa[8];
            aa[0] = pack2(a0.x, a0.x); aa[1] = pack2(a0.y, a0.y);
            aa[2] = pack2(a0.z, a0.z); aa[3] = pack2(a0.w, a0.w);
            aa[4] = pack2(a1.x, a1.x); aa[5] = pack2(a1.y, a1.y);
            aa[6] = pack2(a1.z, a1.z); aa[7] = pack2(a1.w, a1.w);
            if (TN == 8) {
                ulonglong2 bp0 = *(const ulonglong2*)&Bs[kk][tx * 8];
                ulonglong2 bp1 = *(const ulonglong2*)&Bs[kk][tx * 8 + 4];
                ull bb[4] = {bp0.x, bp0.y, bp1.x, bp1.y};
#pragma unroll
                for (int i = 0; i < 8; i++)
#pragma unroll
                    for (int j = 0; j < TN / 2; j++) ffma2(acc[i][j], aa[i], bb[j]);
            } else {
                ull bb = *(const ull*)&Bs[kk][tx * 2];
#pragma unroll
                for (int i = 0; i < 8; i++) ffma2(acc[i][0], aa[i], bb);
            }
        }
        __syncthreads();
    }
#pragma unroll
    for (int i = 0; i < 8; i++) {
        int row = row0 + ty * 8 + i;
        if (row < M) {
            if (TN == 8) {
                float2 p0 = unpack2(acc[i][0]);
                float2 p1 = unpack2(acc[i][1]);
                float2 p2 = unpack2(acc[i][2]);
                float2 p3 = unpack2(acc[i][3]);
                float4 o0 = make_float4(p0.x, p0.y, p1.x, p1.y);
                float4 o1 = make_float4(p2.x, p2.y, p3.x, p3.y);
                *(float4*)(C + row * BN + tx * 8) = o0;
                *(float4*)(C + row * BN + tx * 8 + 4) = o1;
            } else {
                float2 p = unpack2(acc[i][0]);
                *(float2*)(C + row * BN + tx * 2) = p;
            }
        }
    }
}

// ---------------- el/er: per (node,head) attention scores ----------------
template <int H, int D, int F>
__global__ void elr_kernel(const float* __restrict__ feat, const float* __restrict__ al,
                           const float* __restrict__ ar, float* __restrict__ el,
                           float* __restrict__ er) {
    int i = blockIdx.x * blockDim.x + threadIdx.x;
    if (i >= N_NODES * H) return;
    int n = i / H, h = i % H;
    const float4* f4 = (const float4*)(feat + n * F + h * D);
    const float4* a4 = (const float4*)(al + h * D);
    const float4* r4 = (const float4*)(ar + h * D);
    float sl = 0.f, sr = 0.f;
#pragma unroll
    for (int d = 0; d < D / 4; d++) {
        float4 f = f4[d], a = a4[d], r = r4[d];
        sl += f.x * a.x + f.y * a.y + f.z * a.z + f.w * a.w;
        sr += f.x * r.x + f.y * r.y + f.z * r.z + f.w * r.w;
    }
    el[i] = sl;
    er[i] = sr;
}

// ---------------- aggregation (H=4, D=32), fused softmax weights ----------------
__global__ void agg4_kernel(const float* __restrict__ feat, const float* __restrict__ el,
                            const float* __restrict__ er, const float* __restrict__ bias,
                            float* __restrict__ out) {
    int n = blockIdx.x * (blockDim.x >> 5) + (threadIdx.x >> 5);
    int lane = threadIdx.x & 31;
    if (n >= N_NODES) return;
    int start = g_rowptr[n], end = g_rowptr[n + 1];
    int head = lane >> 3;
    float ern = __ldg(&er[n * 4 + head]);

    float4 acc = make_float4(0.f, 0.f, 0.f, 0.f);
    float denom = 0.f;
    int e = start;
    for (; e + 2 <= end; e += 2) {
        int s0 = __ldg(&g_csr[e]);
        int s1 = __ldg(&g_csr[e + 1]);
        float sc0 = __ldg(&el[s0 * 4 + head]) + ern;
        float sc1 = __ldg(&el[s1 * 4 + head]) + ern;
        sc0 = sc0 > 0.f ? sc0 : 0.2f * sc0;
        sc1 = sc1 > 0.f ? sc1 : 0.2f * sc1;
        float w0 = __expf(sc0);
        float w1 = __expf(sc1);
        float4 f0 = *(const float4*)(feat + s0 * 128 + lane * 4);
        float4 f1 = *(const float4*)(feat + s1 * 128 + lane * 4);
        acc.x += w0 * f0.x + w1 * f1.x;
        acc.y += w0 * f0.y + w1 * f1.y;
        acc.z += w0 * f0.z + w1 * f1.z;
        acc.w += w0 * f0.w + w1 * f1.w;
        denom += w0 + w1;
    }
    if (e < end) {
        int s0 = __ldg(&g_csr[e]);
        float sc0 = __ldg(&el[s0 * 4 + head]) + ern;
        sc0 = sc0 > 0.f ? sc0 : 0.2f * sc0;
        float w0 = __expf(sc0);
        float4 f0 = *(const float4*)(feat + s0 * 128 + lane * 4);
        acc.x += w0 * f0.x;
        acc.y += w0 * f0.y;
        acc.z += w0 * f0.z;
        acc.w += w0 * f0.w;
        denom += w0;
    }
    float4 b = *(const float4*)(bias + lane * 4);
    if (end > start) {
        float inv = 1.f / denom;
        b.x += acc.x * inv;
        b.y += acc.y * inv;
        b.z += acc.z * inv;
        b.w += acc.w * inv;
    }
    *(float4*)(out + n * 128 + lane * 4) = b;
}

// ---------------- aggregation (H=1, D=32), fused weights ----------------
__global__ void agg1_kernel(const float* __restrict__ feat, const float* __restrict__ el,
                            const float* __restrict__ er, const float* __restrict__ bias,
                            float* __restrict__ out) {
    int n = blockIdx.x * (blockDim.x >> 5) + (threadIdx.x >> 5);
    int lane = threadIdx.x & 31;
    if (n >= N_NODES) return;
    int start = g_rowptr[n], end = g_rowptr[n + 1];
    float ern = __ldg(&er[n]);

    float acc = 0.f, denom = 0.f;
    int e = start;
    for (; e + 2 <= end; e += 2) {
        int s0 = __ldg(&g_csr[e]);
        int s1 = __ldg(&g_csr[e + 1]);
        float sc0 = __ldg(&el[s0]) + ern;
        float sc1 = __ldg(&el[s1]) + ern;
        sc0 = sc0 > 0.f ? sc0 : 0.2f * sc0;
        sc1 = sc1 > 0.f ? sc1 : 0.2f * sc1;
        float w0 = __expf(sc0);
        float w1 = __expf(sc1);
        acc += w0 * __ldg(feat + s0 * 32 + lane) + w1 * __ldg(feat + s1 * 32 + lane);
        denom += w0 + w1;
    }
    if (e < end) {
        int s0 = __ldg(&g_csr[e]);
        float sc0 = __ldg(&el[s0]) + ern;
        sc0 = sc0 > 0.f ? sc0 : 0.2f * sc0;
        float w0 = __expf(sc0);
        acc += w0 * __ldg(feat + s0 * 32 + lane);
        denom += w0;
    }
    float o = bias[lane];
    if (end > start) o += acc / denom;
    out[n * 32 + lane] = o;
}

// ---------------- batch norm ----------------
__global__ void bn_stats_kernel(const float* __restrict__ h, int off) {
    int c = threadIdx.x;
    float s = 0.f, s2 = 0.f;
    for (int r = blockIdx.x; r < N_NODES; r += gridDim.x) {
        float v = h[r * 128 + c];
        s += v;
        s2 += v * v;
    }
    atomicAdd(&g_bn[off + c], s);
    atomicAdd(&g_bn[off + 128 + c], s2);
}

__global__ void bn_fin_kernel(int off, const float* __restrict__ gamma,
                              const float* __restrict__ beta) {
    int c = threadIdx.x;
    float mu = g_bn[off + c] * (1.f / N_NODES);
    float var = g_bn[off + 128 + c] * (1.f / N_NODES) - mu * mu;
    float sc = gamma[c] * rsqrtf(var + 1e-5f);
    g_ms[c] = sc;
    g_ms[128 + c] = beta[c] - mu * sc;
}

// ---------------- pooling + classifier ----------------
__global__ void pool_kernel(const float* __restrict__ h2, const int* __restrict__ gid) {
    int i = blockIdx.x * blockDim.x + threadIdx.x;
    if (i >= N_NODES * 32) return;
    int n = i >> 5, c = i & 31;
    atomicAdd(&g_pool[gid[n] * 32 + c], h2[n * 32 + c]);
}

__global__ void cls_kernel(const float* __restrict__ Wc, const float* __restrict__ bc,
                           float* __restrict__ out) {
    int g = blockIdx.x;
    int t = threadIdx.x;
    if (t < 10) {
        float s = bc[t];
#pragma unroll
        for (int k = 0; k < 32; k++) s += g_pool[g * 32 + k] * Wc[k * 10 + t];
        out[g * 10 + t] = s;
    }
}

// ---------------- host launcher ----------------
extern "C" void kernel_launch(void* const* d_in, const int* in_sizes, int n_in,
                              void* d_out, int out_size) {
    const float* x   = (const float*)d_in[0];
    const int* esrc  = (const int*)d_in[1];
    const int* edst  = (const int*)d_in[2];
    const int* gid   = (const int*)d_in[3];
    const float* W0  = (const float*)d_in[4];
    const float* al0 = (const float*)d_in[5];
    const float* ar0 = (const float*)d_in[6];
    const float* b0  = (const float*)d_in[7];
    const float* W1  = (const float*)d_in[8];
    const float* al1 = (const float*)d_in[9];
    const float* ar1 = (const float*)d_in[10];
    const float* b1  = (const float*)d_in[11];
    const float* W2  = (const float*)d_in[12];
    const float* al2 = (const float*)d_in[13];
    const float* ar2 = (const float*)d_in[14];
    const float* b2  = (const float*)d_in[15];
    const float* g0  = (const float*)d_in[16];
    const float* be0 = (const float*)d_in[17];
    const float* g1  = (const float*)d_in[18];
    const float* be1 = (const float*)d_in[19];
    const float* Wc  = (const float*)d_in[20];
    const float* bc  = (const float*)d_in[21];
    float* out = (float*)d_out;

    float *feat, *h, *el, *er;
    cudaGetSymbolAddress((void**)&feat, g_feat);
    cudaGetSymbolAddress((void**)&h, g_h);
    cudaGetSymbolAddress((void**)&el, g_el);
    cudaGetSymbolAddress((void**)&er, g_er);

    // preprocessing: CSR by dst
    zero_kernel<<<(N_NODES + 255) / 256, 256>>>();
    hist_kernel<<<(N_EDGES + 255) / 256, 256>>>(edst);
    scan_reduce_kernel<<<NBLK_SCAN, 512>>>();
    scan_top_kernel<<<1, 128>>>();
    scan_final_kernel<<<NBLK_SCAN, 512>>>();
    scatter_kernel<<<(N_EDGES + 255) / 256, 256>>>(esrc, edst);

    const int gemm_blocks = (N_NODES + 127) / 128;   // 391
    const int nwarp_blocks = (N_NODES + 7) / 8;

    // ---- layer 0 ----
    gemm2_kernel<128, 8, false><<<gemm_blocks, 256>>>(x, W0, feat, N_NODES);
    elr_kernel<4, 32, 128><<<(N_NODES * 4 + 255) / 256, 256>>>(feat, al0, ar0, el, er);
    agg4_kernel<<<nwarp_blocks, 256>>>(feat, el, er, b0, h);
    bn_stats_kernel<<<256, 128>>>(h, 0);
    bn_fin_kernel<<<1, 128>>>(0, g0, be0);

    // ---- layer 1 (BN+ReLU fused into GEMM A-load) ----
    gemm2_kernel<128, 8, true><<<gemm_blocks, 256>>>(h, W1, feat, N_NODES);
    elr_kernel<4, 32, 128><<<(N_NODES * 4 + 255) / 256, 256>>>(feat, al1, ar1, el, er);
    agg4_kernel<<<nwarp_blocks, 256>>>(feat, el, er, b1, h);
    bn_stats_kernel<<<256, 128>>>(h, 256);
    bn_fin_kernel<<<1, 128>>>(256, g1, be1);

    // ---- layer 2 (H=1, D=32; BN+ReLU fused into GEMM A-load) ----
    gemm2_kernel<32, 2, true><<<gemm_blocks, 256>>>(h, W2, feat, N_NODES);
    elr_kernel<1, 32, 32><<<(N_NODES + 255) / 256, 256>>>(feat, al2, ar2, el, er);
    agg1_kernel<<<nwarp_blocks, 256>>>(feat, el, er, b2, h);

    // ---- pooling + classifier ----
    pool_kernel<<<(N_NODES * 32 + 255) / 256, 256>>>(h, gid);
    cls_kernel<<<N_GRAPHS, 32>>>(Wc, bc, out);
}